// round 1
// baseline (speedup 1.0000x reference)
#include <cuda_runtime.h>
#include <math.h>

#define B_  2
#define S_  2048
#define HID 1024
#define NH  16
#define NKV 4
#define HD  64
#define MROWS (B_*S_)   // 4096

// Scratch (no cudaMalloc allowed)
__device__ float g_Q[MROWS * HID];        // [B,S,NH,HD]
__device__ float g_K[MROWS * NKV * HD];   // [B,S,NKV,HD]
__device__ float g_V[MROWS * NKV * HD];
__device__ float g_A[MROWS * HID];        // attention output [B,S,NH,HD]

// ---------------------------------------------------------------------------
// C[M,N] = A[M,K] @ W[N,K]^T   (row-major A and W)
// 128x128 block, K-tile 8, 256 threads, 8x8 microtile.
// M % 128 == 0, N % 128 == 0, K % 8 == 0 (true for all our shapes).
// ---------------------------------------------------------------------------
__global__ __launch_bounds__(256) void sgemm_nt(
    const float* __restrict__ A, const float* __restrict__ W,
    float* __restrict__ C, int M, int N, int K)
{
    __shared__ float As[8][128];
    __shared__ float Bs[8][128];
    const int t  = threadIdx.x;
    const int tx = t & 15;
    const int ty = t >> 4;
    const int lrow = t >> 1;          // 0..127
    const int lcol = (t & 1) * 4;     // 0 or 4

    const float* Ab = A + (size_t)(blockIdx.y * 128) * K;
    const float* Wb = W + (size_t)(blockIdx.x * 128) * K;

    float acc[8][8];
#pragma unroll
    for (int i = 0; i < 8; i++)
#pragma unroll
        for (int j = 0; j < 8; j++) acc[i][j] = 0.f;

    for (int k0 = 0; k0 < K; k0 += 8) {
        float4 av = *(const float4*)(Ab + (size_t)lrow * K + k0 + lcol);
        float4 bv = *(const float4*)(Wb + (size_t)lrow * K + k0 + lcol);
        As[lcol+0][lrow] = av.x; As[lcol+1][lrow] = av.y;
        As[lcol+2][lrow] = av.z; As[lcol+3][lrow] = av.w;
        Bs[lcol+0][lrow] = bv.x; Bs[lcol+1][lrow] = bv.y;
        Bs[lcol+2][lrow] = bv.z; Bs[lcol+3][lrow] = bv.w;
        __syncthreads();
#pragma unroll
        for (int k = 0; k < 8; k++) {
            float a[8], b[8];
            *(float4*)&a[0] = *(const float4*)&As[k][ty*8];
            *(float4*)&a[4] = *(const float4*)&As[k][ty*8+4];
            *(float4*)&b[0] = *(const float4*)&Bs[k][tx*8];
            *(float4*)&b[4] = *(const float4*)&Bs[k][tx*8+4];
#pragma unroll
            for (int i = 0; i < 8; i++)
#pragma unroll
                for (int j = 0; j < 8; j++)
                    acc[i][j] += a[i] * b[j];
        }
        __syncthreads();
    }

    float* Cb = C + (size_t)(blockIdx.y*128 + ty*8) * N + blockIdx.x*128 + tx*8;
#pragma unroll
    for (int i = 0; i < 8; i++) {
        *(float4*)(Cb + (size_t)i*N)     = make_float4(acc[i][0],acc[i][1],acc[i][2],acc[i][3]);
        *(float4*)(Cb + (size_t)i*N + 4) = make_float4(acc[i][4],acc[i][5],acc[i][6],acc[i][7]);
    }
}

// ---------------------------------------------------------------------------
// RoPE in-place on [B,S,heads,HD].  cos/sin are [S,HD] with halves duplicated:
// cos[s,i] == cos[s,i+32].  new_lo = lo*c - hi*s ; new_hi = hi*c + lo*s.
// One thread per (b,s,head,i<32) pair.
// ---------------------------------------------------------------------------
__global__ void rope_kernel(float* __restrict__ q, const float* __restrict__ cosT,
                            const float* __restrict__ sinT, int heads, int total)
{
    int idx = blockIdx.x * blockDim.x + threadIdx.x;
    if (idx >= total) return;
    int i  = idx & 31;
    int h  = (idx >> 5) % heads;
    int bs = idx / (32 * heads);
    int s  = bs % S_;
    float c  = cosT[s*HD + i];
    float sn = sinT[s*HD + i];
    float* p = q + ((size_t)bs*heads + h) * HD;
    float lo = p[i], hi = p[i+32];
    p[i]    = lo*c - hi*sn;
    p[i+32] = hi*c + lo*sn;
}

// ---------------------------------------------------------------------------
// Causal flash attention, fp32.
// grid (S/64, NH, B), 256 threads.  BM=64 queries, BN=32 keys per tile.
// Thread t: row = t>>2 (query row in block), dseg = t&3.
//   scores: keys [dseg*8, dseg*8+8);  output: dims [dseg*16, dseg*16+16).
// Row-reductions via shfl among the 4 consecutive lanes of a row.
// ---------------------------------------------------------------------------
#define BM 64
#define BN 32
#define QSTR 68   // smem row stride (floats), 16B-aligned, conflict-free rows
#define PSTR 33

__global__ __launch_bounds__(256) void flash_attn(
    const float* __restrict__ Q, const float* __restrict__ K,
    const float* __restrict__ V, float* __restrict__ O)
{
    __shared__ float Qs[BM*QSTR];
    __shared__ float Ks[BN*QSTR];
    __shared__ float Vs[BN*QSTR];
    __shared__ float Ps[BM*PSTR];

    const int bm = blockIdx.x;
    const int h  = blockIdx.y;
    const int b  = blockIdx.z;
    const int hk = h >> 2;                 // GQA: q head h uses kv head h/4
    const int t  = threadIdx.x;
    const int row  = t >> 2;
    const int dseg = t & 3;
    const int qi = bm*BM + row;

    // Load Q tile (64 rows x 64 floats) as float4
    for (int l = t; l < BM*16; l += 256) {
        int r  = l >> 4;
        int c4 = (l & 15) * 4;
        float4 v4 = *(const float4*)(Q + (((size_t)(b*S_ + bm*BM + r)*NH + h) << 6) + c4);
        float* dst = &Qs[r*QSTR + c4];
        dst[0]=v4.x; dst[1]=v4.y; dst[2]=v4.z; dst[3]=v4.w;
    }

    float m = -1e30f, lsum = 0.f;
    float acc[16];
#pragma unroll
    for (int i = 0; i < 16; i++) acc[i] = 0.f;

    const int ntiles = (bm + 1) * (BM / BN);   // keys up to (bm+1)*64
    for (int tile = 0; tile < ntiles; tile++) {
        const int t0 = tile * BN;
        __syncthreads();   // previous tile's Ks/Vs/Ps reads done (also covers Q load)
        // Load K,V tiles (32 rows x 64 floats each)
        for (int l = t; l < BN*16; l += 256) {
            int r  = l >> 4;
            int c4 = (l & 15) * 4;
            size_t gb = (((size_t)(b*S_ + t0 + r)*NKV + hk) << 6) + c4;
            float4 kv = *(const float4*)(K + gb);
            float4 vv = *(const float4*)(V + gb);
            float* kd = &Ks[r*QSTR + c4];
            kd[0]=kv.x; kd[1]=kv.y; kd[2]=kv.z; kd[3]=kv.w;
            float* vd = &Vs[r*QSTR + c4];
            vd[0]=vv.x; vd[1]=vv.y; vd[2]=vv.z; vd[3]=vv.w;
        }
        __syncthreads();

        // ---- scores S = Q K^T / 8 for this thread's 8 keys ----
        const int j0 = dseg * 8;
        float s[8];
#pragma unroll
        for (int j = 0; j < 8; j++) s[j] = 0.f;
#pragma unroll
        for (int d4 = 0; d4 < HD; d4 += 4) {
            float4 qv = *(const float4*)&Qs[row*QSTR + d4];
#pragma unroll
            for (int j = 0; j < 8; j++) {
                float4 kv = *(const float4*)&Ks[(j0+j)*QSTR + d4];
                s[j] += qv.x*kv.x + qv.y*kv.y + qv.z*kv.z + qv.w*kv.w;
            }
        }
        float mt = -1e30f;
#pragma unroll
        for (int j = 0; j < 8; j++) {
            s[j] *= 0.125f;                       // 1/sqrt(64)
            if (t0 + j0 + j > qi) s[j] = -1e30f;  // causal mask
            mt = fmaxf(mt, s[j]);
        }
        mt = fmaxf(mt, __shfl_xor_sync(0xffffffffu, mt, 1));
        mt = fmaxf(mt, __shfl_xor_sync(0xffffffffu, mt, 2));
        const float mnew = fmaxf(m, mt);
        const float corr = __expf(m - mnew);
        float psum = 0.f;
#pragma unroll
        for (int j = 0; j < 8; j++) {
            float p = __expf(s[j] - mnew);
            psum += p;
            Ps[row*PSTR + j0 + j] = p;
        }
        psum += __shfl_xor_sync(0xffffffffu, psum, 1);
        psum += __shfl_xor_sync(0xffffffffu, psum, 2);
        lsum = lsum * corr + psum;
        m = mnew;
#pragma unroll
        for (int i = 0; i < 16; i++) acc[i] *= corr;
        __syncwarp();   // Ps row written/read by the same 4 lanes' warp

        // ---- acc += P V for this thread's 16 dims ----
        const int d0 = dseg * 16;
#pragma unroll
        for (int j = 0; j < BN; j++) {
            float p = Ps[row*PSTR + j];
#pragma unroll
            for (int q4 = 0; q4 < 16; q4 += 4) {
                float4 vv = *(const float4*)&Vs[j*QSTR + d0 + q4];
                acc[q4+0] += p * vv.x;
                acc[q4+1] += p * vv.y;
                acc[q4+2] += p * vv.z;
                acc[q4+3] += p * vv.w;
            }
        }
    }

    const float inv = 1.f / lsum;
    float* o = O + (((size_t)(b*S_ + qi)*NH + h) << 6) + dseg*16;
#pragma unroll
    for (int dd = 0; dd < 16; dd++) o[dd] = acc[dd] * inv;
}

// ---------------------------------------------------------------------------
extern "C" void kernel_launch(void* const* d_in, const int* in_sizes, int n_in,
                              void* d_out, int out_size)
{
    const float* x    = (const float*)d_in[0];
    const float* cosT = (const float*)d_in[1];
    const float* sinT = (const float*)d_in[2];
    const float* wq   = (const float*)d_in[3];
    const float* wk   = (const float*)d_in[4];
    const float* wv   = (const float*)d_in[5];
    const float* wo   = (const float*)d_in[6];
    float* out = (float*)d_out;

    float *Q, *K, *V, *Aat;
    cudaGetSymbolAddress((void**)&Q,   g_Q);
    cudaGetSymbolAddress((void**)&K,   g_K);
    cudaGetSymbolAddress((void**)&V,   g_V);
    cudaGetSymbolAddress((void**)&Aat, g_A);

    // Projections
    sgemm_nt<<<dim3(HID/128,       MROWS/128), 256>>>(x, wq, Q, MROWS, HID,     HID);
    sgemm_nt<<<dim3((NKV*HD)/128,  MROWS/128), 256>>>(x, wk, K, MROWS, NKV*HD,  HID);
    sgemm_nt<<<dim3((NKV*HD)/128,  MROWS/128), 256>>>(x, wv, V, MROWS, NKV*HD,  HID);

    // RoPE on Q and K
    int totq = MROWS * NH  * 32;
    int totk = MROWS * NKV * 32;
    rope_kernel<<<(totq+255)/256, 256>>>(Q, cosT, sinT, NH,  totq);
    rope_kernel<<<(totk+255)/256, 256>>>(K, cosT, sinT, NKV, totk);

    // Causal GQA flash attention
    flash_attn<<<dim3(S_/BM, NH, B_), 256>>>(Q, K, V, Aat);

    // Output projection
    sgemm_nt<<<dim3(HID/128, MROWS/128), 256>>>(Aat, wo, out, MROWS, HID, HID);
}

// round 2
// speedup vs baseline: 3.1910x; 3.1910x over previous
#include <cuda_runtime.h>
#include <math.h>

#define B_  2
#define S_  2048
#define HID 1024
#define NH  16
#define NKV 4
#define HD  64
#define MROWS (B_*S_)   // 4096

// Scratch (no cudaMalloc allowed)
__device__ float g_Q[MROWS * HID];        // [B,S,NH,HD]
__device__ float g_K[MROWS * NKV * HD];   // [B,S,NKV,HD]
__device__ float g_V[MROWS * NKV * HD];
__device__ float g_A[MROWS * HID];        // attention output [B,S,NH,HD]

// ---------------------------------------------------------------------------
// C[M,N] = A[M,K] @ W[N,K]^T   (row-major A and W)   -- unchanged from R1
// ---------------------------------------------------------------------------
__global__ __launch_bounds__(256) void sgemm_nt(
    const float* __restrict__ A, const float* __restrict__ W,
    float* __restrict__ C, int M, int N, int K)
{
    __shared__ float As[8][128];
    __shared__ float Bs[8][128];
    const int t  = threadIdx.x;
    const int tx = t & 15;
    const int ty = t >> 4;
    const int lrow = t >> 1;          // 0..127
    const int lcol = (t & 1) * 4;     // 0 or 4

    const float* Ab = A + (size_t)(blockIdx.y * 128) * K;
    const float* Wb = W + (size_t)(blockIdx.x * 128) * K;

    float acc[8][8];
#pragma unroll
    for (int i = 0; i < 8; i++)
#pragma unroll
        for (int j = 0; j < 8; j++) acc[i][j] = 0.f;

    for (int k0 = 0; k0 < K; k0 += 8) {
        float4 av = *(const float4*)(Ab + (size_t)lrow * K + k0 + lcol);
        float4 bv = *(const float4*)(Wb + (size_t)lrow * K + k0 + lcol);
        As[lcol+0][lrow] = av.x; As[lcol+1][lrow] = av.y;
        As[lcol+2][lrow] = av.z; As[lcol+3][lrow] = av.w;
        Bs[lcol+0][lrow] = bv.x; Bs[lcol+1][lrow] = bv.y;
        Bs[lcol+2][lrow] = bv.z; Bs[lcol+3][lrow] = bv.w;
        __syncthreads();
#pragma unroll
        for (int k = 0; k < 8; k++) {
            float a[8], b[8];
            *(float4*)&a[0] = *(const float4*)&As[k][ty*8];
            *(float4*)&a[4] = *(const float4*)&As[k][ty*8+4];
            *(float4*)&b[0] = *(const float4*)&Bs[k][tx*8];
            *(float4*)&b[4] = *(const float4*)&Bs[k][tx*8+4];
#pragma unroll
            for (int i = 0; i < 8; i++)
#pragma unroll
                for (int j = 0; j < 8; j++)
                    acc[i][j] += a[i] * b[j];
        }
        __syncthreads();
    }

    float* Cb = C + (size_t)(blockIdx.y*128 + ty*8) * N + blockIdx.x*128 + tx*8;
#pragma unroll
    for (int i = 0; i < 8; i++) {
        *(float4*)(Cb + (size_t)i*N)     = make_float4(acc[i][0],acc[i][1],acc[i][2],acc[i][3]);
        *(float4*)(Cb + (size_t)i*N + 4) = make_float4(acc[i][4],acc[i][5],acc[i][6],acc[i][7]);
    }
}

// ---------------------------------------------------------------------------
// RoPE in-place on [B,S,heads,HD] -- unchanged from R1
// ---------------------------------------------------------------------------
__global__ void rope_kernel(float* __restrict__ q, const float* __restrict__ cosT,
                            const float* __restrict__ sinT, int heads, int total)
{
    int idx = blockIdx.x * blockDim.x + threadIdx.x;
    if (idx >= total) return;
    int i  = idx & 31;
    int h  = (idx >> 5) % heads;
    int bs = idx / (32 * heads);
    int s  = bs % S_;
    float c  = cosT[s*HD + i];
    float sn = sinT[s*HD + i];
    float* p = q + ((size_t)bs*heads + h) * HD;
    float lo = p[i], hi = p[i+32];
    p[i]    = lo*c - hi*sn;
    p[i+32] = hi*c + lo*sn;
}

// ---------------------------------------------------------------------------
// Causal flash attention v2, fp32, register-blocked.
// grid (S/64, NH, B), 256 threads as 16x16 (tx, ty).
// Tile: BM=64 queries x BN=64 keys. Each thread:
//   QK: 4 rows (ty*4+i) x 4 keys (j*16+tx) score microtile
//   PV: 4 rows x 4 dims (tx*4+j) output microtile
// P exchange stays within one warp (same ty group owns the same rows).
// Dynamic smem: Qs/Ks/Vs 64x68 + Ps 64x65 = 68,864 B.
// ---------------------------------------------------------------------------
#define FBM 64
#define FBN 64
#define KST 68
#define PST 65
#define FLASH_SMEM ((3*FBM*KST + FBM*PST) * 4)

__global__ __launch_bounds__(256) void flash_attn2(
    const float* __restrict__ Q, const float* __restrict__ K,
    const float* __restrict__ V, float* __restrict__ O)
{
    extern __shared__ float sm[];
    float* Qs = sm;                   // [64][KST]
    float* Ks = Qs + FBM*KST;         // [64][KST]
    float* Vs = Ks + FBM*KST;         // [64][KST]
    float* Ps = Vs + FBM*KST;         // [64][PST]

    const int bm = blockIdx.x;
    const int h  = blockIdx.y;
    const int b  = blockIdx.z;
    const int hk = h >> 2;            // GQA
    const int t  = threadIdx.x;
    const int tx = t & 15;
    const int ty = t >> 4;

    // Load Q tile (64 rows x 64 floats)
    for (int l = t; l < FBM*16; l += 256) {
        int r  = l >> 4;
        int c4 = (l & 15) * 4;
        float4 v4 = *(const float4*)(Q + (((size_t)(b*S_ + bm*FBM + r)*NH + h) << 6) + c4);
        float* dst = &Qs[r*KST + c4];
        dst[0]=v4.x; dst[1]=v4.y; dst[2]=v4.z; dst[3]=v4.w;
    }

    float m[4], lsum[4], acc[4][4];
#pragma unroll
    for (int i = 0; i < 4; i++) {
        m[i] = -1e30f; lsum[i] = 0.f;
#pragma unroll
        for (int j = 0; j < 4; j++) acc[i][j] = 0.f;
    }

    for (int tile = 0; tile <= bm; tile++) {
        __syncthreads();   // prev tile's Ks/Vs/Ps reads done; also covers Q load
        // Load K,V tiles (64 rows x 64 floats each)
        for (int l = t; l < FBN*16; l += 256) {
            int r  = l >> 4;
            int c4 = (l & 15) * 4;
            size_t gb = (((size_t)(b*S_ + tile*FBN + r)*NKV + hk) << 6) + c4;
            float4 kv = *(const float4*)(K + gb);
            float4 vv = *(const float4*)(V + gb);
            float* kd = &Ks[r*KST + c4];
            kd[0]=kv.x; kd[1]=kv.y; kd[2]=kv.z; kd[3]=kv.w;
            float* vd = &Vs[r*KST + c4];
            vd[0]=vv.x; vd[1]=vv.y; vd[2]=vv.z; vd[3]=vv.w;
        }
        __syncthreads();

        // ---- scores: 4x4 microtile, inner-product over d ----
        float s[4][4];
#pragma unroll
        for (int i = 0; i < 4; i++)
#pragma unroll
            for (int j = 0; j < 4; j++) s[i][j] = 0.f;

#pragma unroll
        for (int d4 = 0; d4 < HD; d4 += 4) {
            float4 q[4];
#pragma unroll
            for (int i = 0; i < 4; i++)
                q[i] = *(const float4*)&Qs[(ty*4+i)*KST + d4];
#pragma unroll
            for (int j = 0; j < 4; j++) {
                float4 kv = *(const float4*)&Ks[(j*16+tx)*KST + d4];
#pragma unroll
                for (int i = 0; i < 4; i++)
                    s[i][j] += q[i].x*kv.x + q[i].y*kv.y + q[i].z*kv.z + q[i].w*kv.w;
            }
        }

        // ---- online softmax (row stats across the 16 tx lanes) ----
        const bool diag = (tile == bm);
#pragma unroll
        for (int i = 0; i < 4; i++) {
            const int qi = bm*FBM + ty*4 + i;
            float mt = -1e30f;
#pragma unroll
            for (int j = 0; j < 4; j++) {
                s[i][j] *= 0.125f;   // 1/sqrt(64)
                if (diag && (tile*FBN + j*16 + tx > qi)) s[i][j] = -1e30f;
                mt = fmaxf(mt, s[i][j]);
            }
            mt = fmaxf(mt, __shfl_xor_sync(0xffffffffu, mt, 1));
            mt = fmaxf(mt, __shfl_xor_sync(0xffffffffu, mt, 2));
            mt = fmaxf(mt, __shfl_xor_sync(0xffffffffu, mt, 4));
            mt = fmaxf(mt, __shfl_xor_sync(0xffffffffu, mt, 8));
            const float mnew = fmaxf(m[i], mt);
            const float corr = __expf(m[i] - mnew);
            float ps = 0.f;
#pragma unroll
            for (int j = 0; j < 4; j++) {
                float p = __expf(s[i][j] - mnew);
                ps += p;
                Ps[(ty*4+i)*PST + j*16 + tx] = p;
            }
            ps += __shfl_xor_sync(0xffffffffu, ps, 1);
            ps += __shfl_xor_sync(0xffffffffu, ps, 2);
            ps += __shfl_xor_sync(0xffffffffu, ps, 4);
            ps += __shfl_xor_sync(0xffffffffu, ps, 8);
            lsum[i] = lsum[i]*corr + ps;
            m[i] = mnew;
#pragma unroll
            for (int j = 0; j < 4; j++) acc[i][j] *= corr;
        }
        __syncwarp();   // Ps rows are produced & consumed within the same warp

        // ---- acc += P V : 4 rows x 4 dims per thread ----
#pragma unroll 4
        for (int kk = 0; kk < FBN; kk++) {
            float a0 = Ps[(ty*4+0)*PST + kk];
            float a1 = Ps[(ty*4+1)*PST + kk];
            float a2 = Ps[(ty*4+2)*PST + kk];
            float a3 = Ps[(ty*4+3)*PST + kk];
            float4 v4 = *(const float4*)&Vs[kk*KST + tx*4];
            acc[0][0] += a0*v4.x; acc[0][1] += a0*v4.y; acc[0][2] += a0*v4.z; acc[0][3] += a0*v4.w;
            acc[1][0] += a1*v4.x; acc[1][1] += a1*v4.y; acc[1][2] += a1*v4.z; acc[1][3] += a1*v4.w;
            acc[2][0] += a2*v4.x; acc[2][1] += a2*v4.y; acc[2][2] += a2*v4.z; acc[2][3] += a2*v4.w;
            acc[3][0] += a3*v4.x; acc[3][1] += a3*v4.y; acc[3][2] += a3*v4.z; acc[3][3] += a3*v4.w;
        }
    }

#pragma unroll
    for (int i = 0; i < 4; i++) {
        const float inv = 1.f / lsum[i];
        float* o = O + (((size_t)(b*S_ + bm*FBM + ty*4 + i)*NH + h) << 6) + tx*4;
        *(float4*)o = make_float4(acc[i][0]*inv, acc[i][1]*inv, acc[i][2]*inv, acc[i][3]*inv);
    }
}

// ---------------------------------------------------------------------------
extern "C" void kernel_launch(void* const* d_in, const int* in_sizes, int n_in,
                              void* d_out, int out_size)
{
    const float* x    = (const float*)d_in[0];
    const float* cosT = (const float*)d_in[1];
    const float* sinT = (const float*)d_in[2];
    const float* wq   = (const float*)d_in[3];
    const float* wk   = (const float*)d_in[4];
    const float* wv   = (const float*)d_in[5];
    const float* wo   = (const float*)d_in[6];
    float* out = (float*)d_out;

    float *Q, *K, *V, *Aat;
    cudaGetSymbolAddress((void**)&Q,   g_Q);
    cudaGetSymbolAddress((void**)&K,   g_K);
    cudaGetSymbolAddress((void**)&V,   g_V);
    cudaGetSymbolAddress((void**)&Aat, g_A);

    // Projections
    sgemm_nt<<<dim3(HID/128,       MROWS/128), 256>>>(x, wq, Q, MROWS, HID,     HID);
    sgemm_nt<<<dim3((NKV*HD)/128,  MROWS/128), 256>>>(x, wk, K, MROWS, NKV*HD,  HID);
    sgemm_nt<<<dim3((NKV*HD)/128,  MROWS/128), 256>>>(x, wv, V, MROWS, NKV*HD,  HID);

    // RoPE on Q and K
    int totq = MROWS * NH  * 32;
    int totk = MROWS * NKV * 32;
    rope_kernel<<<(totq+255)/256, 256>>>(Q, cosT, sinT, NH,  totq);
    rope_kernel<<<(totk+255)/256, 256>>>(K, cosT, sinT, NKV, totk);

    // Causal GQA flash attention (dynamic smem > 48KB)
    static bool attr_set = false;
    if (!attr_set) {
        cudaFuncSetAttribute(flash_attn2, cudaFuncAttributeMaxDynamicSharedMemorySize, FLASH_SMEM);
        attr_set = true;
    }
    flash_attn2<<<dim3(S_/FBM, NH, B_), 256, FLASH_SMEM>>>(Q, K, V, Aat);

    // Output projection
    sgemm_nt<<<dim3(HID/128, MROWS/128), 256>>>(Aat, wo, out, MROWS, HID, HID);
}

// round 3
// speedup vs baseline: 5.0637x; 1.5869x over previous
#include <cuda_runtime.h>
#include <math.h>

#define B_  2
#define S_  2048
#define HID 1024
#define NH  16
#define NKV 4
#define HD  64
#define MROWS (B_*S_)   // 4096

// Scratch (no cudaMalloc allowed)
__device__ float g_Q[MROWS * HID];        // [B,S,NH,HD]
__device__ float g_K[MROWS * NKV * HD];   // [B,S,NKV,HD]
__device__ float g_V[MROWS * NKV * HD];
__device__ float g_A[MROWS * HID];        // attention output [B,S,NH,HD]

// ---------------------------------------------------------------------------
// tf32 tensor-core GEMM:  C[M,N] = A[M,K] @ W[N,K]^T  (row-major A and W)
// 128x128 block, BK=32, 256 threads (8 warps), warp tile 64x32,
// mma.sync.aligned.m16n8k8.row.col.f32.tf32.tf32.f32.
// Smem stride 36 floats -> fragment loads are bank-conflict-free.
// M%128==0, N%128==0, K%32==0 (all our shapes qualify).
// ---------------------------------------------------------------------------
#define TST 36

__device__ __forceinline__ unsigned f2tf32(float x) {
    unsigned r;
    asm("cvt.rna.tf32.f32 %0, %1;" : "=r"(r) : "f"(x));
    return r;
}

__global__ __launch_bounds__(256) void sgemm_tf32(
    const float* __restrict__ A, const float* __restrict__ W,
    float* __restrict__ C, int M, int N, int K)
{
    __shared__ unsigned As[128*TST];
    __shared__ unsigned Bs[128*TST];

    const int t    = threadIdx.x;
    const int wid  = t >> 5;
    const int lane = t & 31;
    const int grp  = lane >> 2;     // 0..7
    const int tig  = lane & 3;      // 0..3
    const int wm   = (wid >> 2) * 64;   // warp m offset (0 or 64)
    const int wn   = (wid & 3) * 32;    // warp n offset (0,32,64,96)

    const float* Ab = A + (size_t)(blockIdx.y * 128) * K;
    const float* Wb = W + (size_t)(blockIdx.x * 128) * K;

    float acc[2][4][4][4];   // [dummy m-split? no] -> [mf up to 4][nf 4][4]
    // warp tile 64x32: mf 0..3 (16 rows each), nf 0..3 (8 cols each)
#pragma unroll
    for (int mf = 0; mf < 2; mf++)
#pragma unroll
        for (int nf = 0; nf < 4; nf++)
#pragma unroll
            for (int r = 0; r < 4; r++) {
                acc[mf][nf][r][0] = 0.f; acc[mf][nf][r][1] = 0.f;
                acc[mf][nf][r][2] = 0.f; acc[mf][nf][r][3] = 0.f;
            }
    // NOTE: acc indexed [mf2][nf][k-sub?] -- we use mf in 0..3 via pairs below.
    // To keep register layout simple we re-dimension: acc[mf/2][nf][(mf&1)*?]...
    // Simpler: use acc4 array of [4][4][4] flattened:
    // (declared above as [2][4][4][4] = 128 floats; mf = mf2*2+ms)

    for (int k0 = 0; k0 < K; k0 += 32) {
        // load A,B 128x32 tiles, converting to tf32
#pragma unroll
        for (int i = 0; i < 4; i++) {
            int idx = t + i * 256;
            int r   = idx >> 3;
            int c4  = (idx & 7) * 4;
            float4 av = *(const float4*)(Ab + (size_t)r * K + k0 + c4);
            float4 bv = *(const float4*)(Wb + (size_t)r * K + k0 + c4);
            unsigned* ad = &As[r*TST + c4];
            ad[0]=f2tf32(av.x); ad[1]=f2tf32(av.y); ad[2]=f2tf32(av.z); ad[3]=f2tf32(av.w);
            unsigned* bd = &Bs[r*TST + c4];
            bd[0]=f2tf32(bv.x); bd[1]=f2tf32(bv.y); bd[2]=f2tf32(bv.z); bd[3]=f2tf32(bv.w);
        }
        __syncthreads();

#pragma unroll
        for (int k8 = 0; k8 < 4; k8++) {
            const int kb = k8 * 8;
            unsigned af[4][4];   // [mf][4 regs]
            unsigned bf[4][2];   // [nf][2 regs]
#pragma unroll
            for (int mf = 0; mf < 4; mf++) {
                int m = wm + mf*16 + grp;
                af[mf][0] = As[(m  )*TST + kb + tig];
                af[mf][1] = As[(m+8)*TST + kb + tig];
                af[mf][2] = As[(m  )*TST + kb + tig + 4];
                af[mf][3] = As[(m+8)*TST + kb + tig + 4];
            }
#pragma unroll
            for (int nf = 0; nf < 4; nf++) {
                int n = wn + nf*8 + grp;
                bf[nf][0] = Bs[n*TST + kb + tig];
                bf[nf][1] = Bs[n*TST + kb + tig + 4];
            }
#pragma unroll
            for (int mf = 0; mf < 4; mf++) {
#pragma unroll
                for (int nf = 0; nf < 4; nf++) {
                    float* c = acc[mf>>1][nf][(mf&1)*2];   // 2 consecutive rows of 4
                    // acc[mf/2][nf][(mf&1)*2 .. +1] holds the 4 regs as 2x float2?  -> use full 4:
                    float* c0 = &acc[mf>>1][nf][(mf&1)*2][0];
                    (void)c;
                    asm volatile(
                        "mma.sync.aligned.m16n8k8.row.col.f32.tf32.tf32.f32 "
                        "{%0,%1,%2,%3}, {%4,%5,%6,%7}, {%8,%9}, {%0,%1,%2,%3};"
                        : "+f"(c0[0]), "+f"(c0[1]), "+f"(c0[2]), "+f"(c0[3])
                        : "r"(af[mf][0]), "r"(af[mf][1]), "r"(af[mf][2]), "r"(af[mf][3]),
                          "r"(bf[nf][0]), "r"(bf[nf][1]));
                }
            }
        }
        __syncthreads();
    }

    // epilogue
#pragma unroll
    for (int mf = 0; mf < 4; mf++) {
#pragma unroll
        for (int nf = 0; nf < 4; nf++) {
            float* c0 = &acc[mf>>1][nf][(mf&1)*2][0];
            int row = blockIdx.y*128 + wm + mf*16 + grp;
            int col = blockIdx.x*128 + wn + nf*8 + tig*2;
            *(float2*)(C + (size_t)row*N + col)     = make_float2(c0[0], c0[1]);
            *(float2*)(C + (size_t)(row+8)*N + col) = make_float2(c0[2], c0[3]);
        }
    }
}

// ---------------------------------------------------------------------------
// RoPE in-place on [B,S,heads,HD] -- unchanged
// ---------------------------------------------------------------------------
__global__ void rope_kernel(float* __restrict__ q, const float* __restrict__ cosT,
                            const float* __restrict__ sinT, int heads, int total)
{
    int idx = blockIdx.x * blockDim.x + threadIdx.x;
    if (idx >= total) return;
    int i  = idx & 31;
    int h  = (idx >> 5) % heads;
    int bs = idx / (32 * heads);
    int s  = bs % S_;
    float c  = cosT[s*HD + i];
    float sn = sinT[s*HD + i];
    float* p = q + ((size_t)bs*heads + h) * HD;
    float lo = p[i], hi = p[i+32];
    p[i]    = lo*c - hi*sn;
    p[i+32] = hi*c + lo*sn;
}

// ---------------------------------------------------------------------------
// Causal flash attention v2, fp32, register-blocked -- unchanged from R2
// ---------------------------------------------------------------------------
#define FBM 64
#define FBN 64
#define KST 68
#define PST 65
#define FLASH_SMEM ((3*FBM*KST + FBM*PST) * 4)

__global__ __launch_bounds__(256) void flash_attn2(
    const float* __restrict__ Q, const float* __restrict__ K,
    const float* __restrict__ V, float* __restrict__ O)
{
    extern __shared__ float sm[];
    float* Qs = sm;
    float* Ks = Qs + FBM*KST;
    float* Vs = Ks + FBM*KST;
    float* Ps = Vs + FBM*KST;

    const int bm = blockIdx.x;
    const int h  = blockIdx.y;
    const int b  = blockIdx.z;
    const int hk = h >> 2;
    const int t  = threadIdx.x;
    const int tx = t & 15;
    const int ty = t >> 4;

    for (int l = t; l < FBM*16; l += 256) {
        int r  = l >> 4;
        int c4 = (l & 15) * 4;
        float4 v4 = *(const float4*)(Q + (((size_t)(b*S_ + bm*FBM + r)*NH + h) << 6) + c4);
        float* dst = &Qs[r*KST + c4];
        dst[0]=v4.x; dst[1]=v4.y; dst[2]=v4.z; dst[3]=v4.w;
    }

    float m[4], lsum[4], acc[4][4];
#pragma unroll
    for (int i = 0; i < 4; i++) {
        m[i] = -1e30f; lsum[i] = 0.f;
#pragma unroll
        for (int j = 0; j < 4; j++) acc[i][j] = 0.f;
    }

    for (int tile = 0; tile <= bm; tile++) {
        __syncthreads();
        for (int l = t; l < FBN*16; l += 256) {
            int r  = l >> 4;
            int c4 = (l & 15) * 4;
            size_t gb = (((size_t)(b*S_ + tile*FBN + r)*NKV + hk) << 6) + c4;
            float4 kv = *(const float4*)(K + gb);
            float4 vv = *(const float4*)(V + gb);
            float* kd = &Ks[r*KST + c4];
            kd[0]=kv.x; kd[1]=kv.y; kd[2]=kv.z; kd[3]=kv.w;
            float* vd = &Vs[r*KST + c4];
            vd[0]=vv.x; vd[1]=vv.y; vd[2]=vv.z; vd[3]=vv.w;
        }
        __syncthreads();

        float s[4][4];
#pragma unroll
        for (int i = 0; i < 4; i++)
#pragma unroll
            for (int j = 0; j < 4; j++) s[i][j] = 0.f;

#pragma unroll
        for (int d4 = 0; d4 < HD; d4 += 4) {
            float4 q[4];
#pragma unroll
            for (int i = 0; i < 4; i++)
                q[i] = *(const float4*)&Qs[(ty*4+i)*KST + d4];
#pragma unroll
            for (int j = 0; j < 4; j++) {
                float4 kv = *(const float4*)&Ks[(j*16+tx)*KST + d4];
#pragma unroll
                for (int i = 0; i < 4; i++)
                    s[i][j] += q[i].x*kv.x + q[i].y*kv.y + q[i].z*kv.z + q[i].w*kv.w;
            }
        }

        const bool diag = (tile == bm);
#pragma unroll
        for (int i = 0; i < 4; i++) {
            const int qi = bm*FBM + ty*4 + i;
            float mt = -1e30f;
#pragma unroll
            for (int j = 0; j < 4; j++) {
                s[i][j] *= 0.125f;
                if (diag && (tile*FBN + j*16 + tx > qi)) s[i][j] = -1e30f;
                mt = fmaxf(mt, s[i][j]);
            }
            mt = fmaxf(mt, __shfl_xor_sync(0xffffffffu, mt, 1));
            mt = fmaxf(mt, __shfl_xor_sync(0xffffffffu, mt, 2));
            mt = fmaxf(mt, __shfl_xor_sync(0xffffffffu, mt, 4));
            mt = fmaxf(mt, __shfl_xor_sync(0xffffffffu, mt, 8));
            const float mnew = fmaxf(m[i], mt);
            const float corr = __expf(m[i] - mnew);
            float ps = 0.f;
#pragma unroll
            for (int j = 0; j < 4; j++) {
                float p = __expf(s[i][j] - mnew);
                ps += p;
                Ps[(ty*4+i)*PST + j*16 + tx] = p;
            }
            ps += __shfl_xor_sync(0xffffffffu, ps, 1);
            ps += __shfl_xor_sync(0xffffffffu, ps, 2);
            ps += __shfl_xor_sync(0xffffffffu, ps, 4);
            ps += __shfl_xor_sync(0xffffffffu, ps, 8);
            lsum[i] = lsum[i]*corr + ps;
            m[i] = mnew;
#pragma unroll
            for (int j = 0; j < 4; j++) acc[i][j] *= corr;
        }
        __syncwarp();

#pragma unroll 4
        for (int kk = 0; kk < FBN; kk++) {
            float a0 = Ps[(ty*4+0)*PST + kk];
            float a1 = Ps[(ty*4+1)*PST + kk];
            float a2 = Ps[(ty*4+2)*PST + kk];
            float a3 = Ps[(ty*4+3)*PST + kk];
            float4 v4 = *(const float4*)&Vs[kk*KST + tx*4];
            acc[0][0] += a0*v4.x; acc[0][1] += a0*v4.y; acc[0][2] += a0*v4.z; acc[0][3] += a0*v4.w;
            acc[1][0] += a1*v4.x; acc[1][1] += a1*v4.y; acc[1][2] += a1*v4.z; acc[1][3] += a1*v4.w;
            acc[2][0] += a2*v4.x; acc[2][1] += a2*v4.y; acc[2][2] += a2*v4.z; acc[2][3] += a2*v4.w;
            acc[3][0] += a3*v4.x; acc[3][1] += a3*v4.y; acc[3][2] += a3*v4.z; acc[3][3] += a3*v4.w;
        }
    }

#pragma unroll
    for (int i = 0; i < 4; i++) {
        const float inv = 1.f / lsum[i];
        float* o = O + (((size_t)(b*S_ + bm*FBM + ty*4 + i)*NH + h) << 6) + tx*4;
        *(float4*)o = make_float4(acc[i][0]*inv, acc[i][1]*inv, acc[i][2]*inv, acc[i][3]*inv);
    }
}

// ---------------------------------------------------------------------------
extern "C" void kernel_launch(void* const* d_in, const int* in_sizes, int n_in,
                              void* d_out, int out_size)
{
    const float* x    = (const float*)d_in[0];
    const float* cosT = (const float*)d_in[1];
    const float* sinT = (const float*)d_in[2];
    const float* wq   = (const float*)d_in[3];
    const float* wk   = (const float*)d_in[4];
    const float* wv   = (const float*)d_in[5];
    const float* wo   = (const float*)d_in[6];
    float* out = (float*)d_out;

    float *Q, *K, *V, *Aat;
    cudaGetSymbolAddress((void**)&Q,   g_Q);
    cudaGetSymbolAddress((void**)&K,   g_K);
    cudaGetSymbolAddress((void**)&V,   g_V);
    cudaGetSymbolAddress((void**)&Aat, g_A);

    // Projections (tf32 tensor cores)
    sgemm_tf32<<<dim3(HID/128,       MROWS/128), 256>>>(x, wq, Q, MROWS, HID,     HID);
    sgemm_tf32<<<dim3((NKV*HD)/128,  MROWS/128), 256>>>(x, wk, K, MROWS, NKV*HD,  HID);
    sgemm_tf32<<<dim3((NKV*HD)/128,  MROWS/128), 256>>>(x, wv, V, MROWS, NKV*HD,  HID);

    // RoPE on Q and K
    int totq = MROWS * NH  * 32;
    int totk = MROWS * NKV * 32;
    rope_kernel<<<(totq+255)/256, 256>>>(Q, cosT, sinT, NH,  totq);
    rope_kernel<<<(totk+255)/256, 256>>>(K, cosT, sinT, NKV, totk);

    // Causal GQA flash attention
    static bool attr_set = false;
    if (!attr_set) {
        cudaFuncSetAttribute(flash_attn2, cudaFuncAttributeMaxDynamicSharedMemorySize, FLASH_SMEM);
        attr_set = true;
    }
    flash_attn2<<<dim3(S_/FBM, NH, B_), 256, FLASH_SMEM>>>(Q, K, V, Aat);

    // Output projection (tf32 tensor cores)
    sgemm_tf32<<<dim3(HID/128, MROWS/128), 256>>>(Aat, wo, out, MROWS, HID, HID);
}

// round 4
// speedup vs baseline: 9.2580x; 1.8283x over previous
#include <cuda_runtime.h>
#include <math.h>

#define B_  2
#define S_  2048
#define HID 1024
#define NH  16
#define NKV 4
#define HD  64
#define MROWS (B_*S_)   // 4096

// Scratch (no cudaMalloc allowed)
__device__ float g_Q[MROWS * HID];        // [B,S,NH,HD]
__device__ float g_K[MROWS * NKV * HD];   // [B,S,NKV,HD]
__device__ float g_V[MROWS * NKV * HD];
__device__ float g_A[MROWS * HID];        // attention output [B,S,NH,HD]

__device__ __forceinline__ unsigned f2tf32(float x) {
    unsigned r;
    asm("cvt.rna.tf32.f32 %0, %1;" : "=r"(r) : "f"(x));
    return r;
}

// ---------------------------------------------------------------------------
// tf32 tensor-core GEMM:  C[M,N] = A[M,K] @ W[N,K]^T   -- unchanged from R3
// ---------------------------------------------------------------------------
#define TST 36

__global__ __launch_bounds__(256) void sgemm_tf32(
    const float* __restrict__ A, const float* __restrict__ W,
    float* __restrict__ C, int M, int N, int K)
{
    __shared__ unsigned As[128*TST];
    __shared__ unsigned Bs[128*TST];

    const int t    = threadIdx.x;
    const int wid  = t >> 5;
    const int lane = t & 31;
    const int grp  = lane >> 2;
    const int tig  = lane & 3;
    const int wm   = (wid >> 2) * 64;
    const int wn   = (wid & 3) * 32;

    const float* Ab = A + (size_t)(blockIdx.y * 128) * K;
    const float* Wb = W + (size_t)(blockIdx.x * 128) * K;

    float acc[2][4][4][4];
#pragma unroll
    for (int mf = 0; mf < 2; mf++)
#pragma unroll
        for (int nf = 0; nf < 4; nf++)
#pragma unroll
            for (int r = 0; r < 4; r++) {
                acc[mf][nf][r][0] = 0.f; acc[mf][nf][r][1] = 0.f;
                acc[mf][nf][r][2] = 0.f; acc[mf][nf][r][3] = 0.f;
            }

    for (int k0 = 0; k0 < K; k0 += 32) {
#pragma unroll
        for (int i = 0; i < 4; i++) {
            int idx = t + i * 256;
            int r   = idx >> 3;
            int c4  = (idx & 7) * 4;
            float4 av = *(const float4*)(Ab + (size_t)r * K + k0 + c4);
            float4 bv = *(const float4*)(Wb + (size_t)r * K + k0 + c4);
            unsigned* ad = &As[r*TST + c4];
            ad[0]=f2tf32(av.x); ad[1]=f2tf32(av.y); ad[2]=f2tf32(av.z); ad[3]=f2tf32(av.w);
            unsigned* bd = &Bs[r*TST + c4];
            bd[0]=f2tf32(bv.x); bd[1]=f2tf32(bv.y); bd[2]=f2tf32(bv.z); bd[3]=f2tf32(bv.w);
        }
        __syncthreads();

#pragma unroll
        for (int k8 = 0; k8 < 4; k8++) {
            const int kb = k8 * 8;
            unsigned af[4][4];
            unsigned bf[4][2];
#pragma unroll
            for (int mf = 0; mf < 4; mf++) {
                int m = wm + mf*16 + grp;
                af[mf][0] = As[(m  )*TST + kb + tig];
                af[mf][1] = As[(m+8)*TST + kb + tig];
                af[mf][2] = As[(m  )*TST + kb + tig + 4];
                af[mf][3] = As[(m+8)*TST + kb + tig + 4];
            }
#pragma unroll
            for (int nf = 0; nf < 4; nf++) {
                int n = wn + nf*8 + grp;
                bf[nf][0] = Bs[n*TST + kb + tig];
                bf[nf][1] = Bs[n*TST + kb + tig + 4];
            }
#pragma unroll
            for (int mf = 0; mf < 4; mf++) {
#pragma unroll
                for (int nf = 0; nf < 4; nf++) {
                    float* c0 = &acc[mf>>1][nf][(mf&1)*2][0];
                    asm volatile(
                        "mma.sync.aligned.m16n8k8.row.col.f32.tf32.tf32.f32 "
                        "{%0,%1,%2,%3}, {%4,%5,%6,%7}, {%8,%9}, {%0,%1,%2,%3};"
                        : "+f"(c0[0]), "+f"(c0[1]), "+f"(c0[2]), "+f"(c0[3])
                        : "r"(af[mf][0]), "r"(af[mf][1]), "r"(af[mf][2]), "r"(af[mf][3]),
                          "r"(bf[nf][0]), "r"(bf[nf][1]));
                }
            }
        }
        __syncthreads();
    }

#pragma unroll
    for (int mf = 0; mf < 4; mf++) {
#pragma unroll
        for (int nf = 0; nf < 4; nf++) {
            float* c0 = &acc[mf>>1][nf][(mf&1)*2][0];
            int row = blockIdx.y*128 + wm + mf*16 + grp;
            int col = blockIdx.x*128 + wn + nf*8 + tig*2;
            *(float2*)(C + (size_t)row*N + col)     = make_float2(c0[0], c0[1]);
            *(float2*)(C + (size_t)(row+8)*N + col) = make_float2(c0[2], c0[3]);
        }
    }
}

// ---------------------------------------------------------------------------
// RoPE in-place on [B,S,heads,HD] -- unchanged
// ---------------------------------------------------------------------------
__global__ void rope_kernel(float* __restrict__ q, const float* __restrict__ cosT,
                            const float* __restrict__ sinT, int heads, int total)
{
    int idx = blockIdx.x * blockDim.x + threadIdx.x;
    if (idx >= total) return;
    int i  = idx & 31;
    int h  = (idx >> 5) % heads;
    int bs = idx / (32 * heads);
    int s  = bs % S_;
    float c  = cosT[s*HD + i];
    float sn = sinT[s*HD + i];
    float* p = q + ((size_t)bs*heads + h) * HD;
    float lo = p[i], hi = p[i+32];
    p[i]    = lo*c - hi*sn;
    p[i+32] = hi*c + lo*sn;
}

// ---------------------------------------------------------------------------
// Tensor-core causal flash attention (tf32 mma.sync.m16n8k8).
// grid (NH, S/128, B), 256 threads (8 warps). BM=128 (16 q-rows/warp), BN=64.
// Q: A-fragments in registers (pre-scaled by 1/sqrt(d), tf32).
// K: smem [key][dim] stride 68 (tf32)  -> QK B-fragments, conflict-free.
// V: smem [key][dim] stride 68 (tf32)  -> PV B-fragments, conflict-free.
// P: smem [row][key] stride 68 (tf32)  -> PV A-fragments, conflict-free reads.
// Softmax on the C-fragment layout: each thread owns rows {grp, grp+8},
// cols {nf*8+2tig, +1}; row stats reduced with shfl xor 1,2 (tig lanes).
// ---------------------------------------------------------------------------
#define FST 68
#define FA_SMEM ((64*FST*2 + 128*FST) * 4)   // Ks + Vs + Ps = 69632 B

__global__ __launch_bounds__(256) void flash_attn_mma(
    const float* __restrict__ Q, const float* __restrict__ K,
    const float* __restrict__ V, float* __restrict__ O)
{
    extern __shared__ unsigned fsm[];
    unsigned* Ks = fsm;              // [64][FST]
    unsigned* Vs = Ks + 64*FST;      // [64][FST]
    unsigned* Ps = Vs + 64*FST;      // [128][FST]

    const int h  = blockIdx.x;
    const int bm = (gridDim.y - 1) - blockIdx.y;   // heaviest blocks first
    const int b  = blockIdx.z;
    const int hk = h >> 2;                          // GQA
    const int t    = threadIdx.x;
    const int w    = t >> 5;
    const int lane = t & 31;
    const int grp  = lane >> 2;
    const int tig  = lane & 3;

    const int row0 = bm*128 + w*16 + grp;   // this thread's two q rows
    const int row1 = row0 + 8;

    // ---- Q fragments: 8 k-chunks x 4 regs, scaled by 1/8 and tf32-converted
    unsigned qf[8][4];
    {
        const float* q0 = Q + (((size_t)(b*S_ + row0)*NH + h) << 6);
        const float* q1 = Q + (((size_t)(b*S_ + row1)*NH + h) << 6);
#pragma unroll
        for (int kb = 0; kb < 8; kb++) {
            qf[kb][0] = f2tf32(0.125f * q0[kb*8 + tig]);
            qf[kb][1] = f2tf32(0.125f * q1[kb*8 + tig]);
            qf[kb][2] = f2tf32(0.125f * q0[kb*8 + tig + 4]);
            qf[kb][3] = f2tf32(0.125f * q1[kb*8 + tig + 4]);
        }
    }

    float oacc[8][4];
#pragma unroll
    for (int nf = 0; nf < 8; nf++) {
        oacc[nf][0]=0.f; oacc[nf][1]=0.f; oacc[nf][2]=0.f; oacc[nf][3]=0.f;
    }
    float m0 = -1e30f, m1 = -1e30f, l0 = 0.f, l1 = 0.f;

    const int ntiles = 2*(bm + 1);
    for (int tile = 0; tile < ntiles; tile++) {
        __syncthreads();   // protect Ks/Vs reuse across tiles
        // ---- load K,V tile (64 keys x 64 dims), convert to tf32
#pragma unroll
        for (int i = 0; i < 4; i++) {
            int idx = t + i*256;
            int r   = idx >> 4;
            int c4  = (idx & 15) * 4;
            size_t gb = (((size_t)(b*S_ + tile*64 + r)*NKV + hk) << 6) + c4;
            float4 kv = *(const float4*)(K + gb);
            float4 vv = *(const float4*)(V + gb);
            unsigned* kd = &Ks[r*FST + c4];
            kd[0]=f2tf32(kv.x); kd[1]=f2tf32(kv.y); kd[2]=f2tf32(kv.z); kd[3]=f2tf32(kv.w);
            unsigned* vd = &Vs[r*FST + c4];
            vd[0]=f2tf32(vv.x); vd[1]=f2tf32(vv.y); vd[2]=f2tf32(vv.z); vd[3]=f2tf32(vv.w);
        }
        __syncthreads();

        // ---- S = (Q/8) K^T : per warp 16x64, 8 nf x 8 kb MMAs
        float sacc[8][4];
#pragma unroll
        for (int nf = 0; nf < 8; nf++) {
            sacc[nf][0]=0.f; sacc[nf][1]=0.f; sacc[nf][2]=0.f; sacc[nf][3]=0.f;
        }
#pragma unroll
        for (int kb = 0; kb < 8; kb++) {
#pragma unroll
            for (int nf = 0; nf < 8; nf++) {
                unsigned b0 = Ks[(nf*8+grp)*FST + kb*8 + tig];
                unsigned b1 = Ks[(nf*8+grp)*FST + kb*8 + tig + 4];
                float* c0 = &sacc[nf][0];
                asm volatile(
                    "mma.sync.aligned.m16n8k8.row.col.f32.tf32.tf32.f32 "
                    "{%0,%1,%2,%3}, {%4,%5,%6,%7}, {%8,%9}, {%0,%1,%2,%3};"
                    : "+f"(c0[0]), "+f"(c0[1]), "+f"(c0[2]), "+f"(c0[3])
                    : "r"(qf[kb][0]), "r"(qf[kb][1]), "r"(qf[kb][2]), "r"(qf[kb][3]),
                      "r"(b0), "r"(b1));
            }
        }

        // ---- online softmax on fragment layout
        const bool diag = (tile >= 2*bm);   // only last two tiles can mask
        const int colb = tile*64;
        float mt0 = -1e30f, mt1 = -1e30f;
#pragma unroll
        for (int nf = 0; nf < 8; nf++) {
            const int c0i = colb + nf*8 + tig*2;
            if (diag) {
                if (c0i     > row0) sacc[nf][0] = -1e30f;
                if (c0i + 1 > row0) sacc[nf][1] = -1e30f;
                if (c0i     > row1) sacc[nf][2] = -1e30f;
                if (c0i + 1 > row1) sacc[nf][3] = -1e30f;
            }
            mt0 = fmaxf(mt0, fmaxf(sacc[nf][0], sacc[nf][1]));
            mt1 = fmaxf(mt1, fmaxf(sacc[nf][2], sacc[nf][3]));
        }
        mt0 = fmaxf(mt0, __shfl_xor_sync(0xffffffffu, mt0, 1));
        mt0 = fmaxf(mt0, __shfl_xor_sync(0xffffffffu, mt0, 2));
        mt1 = fmaxf(mt1, __shfl_xor_sync(0xffffffffu, mt1, 1));
        mt1 = fmaxf(mt1, __shfl_xor_sync(0xffffffffu, mt1, 2));

        const float mn0 = fmaxf(m0, mt0);
        const float mn1 = fmaxf(m1, mt1);
        const float cr0 = __expf(m0 - mn0);
        const float cr1 = __expf(m1 - mn1);
        float ps0 = 0.f, ps1 = 0.f;

        unsigned* P0 = &Ps[(w*16 + grp)*FST + tig*2];
        unsigned* P1 = P0 + 8*FST;
#pragma unroll
        for (int nf = 0; nf < 8; nf++) {
            float p00 = __expf(sacc[nf][0] - mn0);
            float p01 = __expf(sacc[nf][1] - mn0);
            float p10 = __expf(sacc[nf][2] - mn1);
            float p11 = __expf(sacc[nf][3] - mn1);
            ps0 += p00 + p01;
            ps1 += p10 + p11;
            uint2 u0 = make_uint2(f2tf32(p00), f2tf32(p01));
            uint2 u1 = make_uint2(f2tf32(p10), f2tf32(p11));
            *(uint2*)(P0 + nf*8) = u0;
            *(uint2*)(P1 + nf*8) = u1;
        }
        ps0 += __shfl_xor_sync(0xffffffffu, ps0, 1);
        ps0 += __shfl_xor_sync(0xffffffffu, ps0, 2);
        ps1 += __shfl_xor_sync(0xffffffffu, ps1, 1);
        ps1 += __shfl_xor_sync(0xffffffffu, ps1, 2);
        l0 = l0*cr0 + ps0;  m0 = mn0;
        l1 = l1*cr1 + ps1;  m1 = mn1;
#pragma unroll
        for (int nf = 0; nf < 8; nf++) {
            oacc[nf][0] *= cr0; oacc[nf][1] *= cr0;
            oacc[nf][2] *= cr1; oacc[nf][3] *= cr1;
        }
        __syncwarp();   // Ps region is warp-private

        // ---- O += P V : 8 nf(dims) x 8 kb(key chunks)
#pragma unroll
        for (int kb = 0; kb < 8; kb++) {
            unsigned a0 = Ps[(w*16 + grp    )*FST + kb*8 + tig];
            unsigned a1 = Ps[(w*16 + grp + 8)*FST + kb*8 + tig];
            unsigned a2 = Ps[(w*16 + grp    )*FST + kb*8 + tig + 4];
            unsigned a3 = Ps[(w*16 + grp + 8)*FST + kb*8 + tig + 4];
#pragma unroll
            for (int nf = 0; nf < 8; nf++) {
                unsigned b0 = Vs[(kb*8 + tig    )*FST + nf*8 + grp];
                unsigned b1 = Vs[(kb*8 + tig + 4)*FST + nf*8 + grp];
                float* c0 = &oacc[nf][0];
                asm volatile(
                    "mma.sync.aligned.m16n8k8.row.col.f32.tf32.tf32.f32 "
                    "{%0,%1,%2,%3}, {%4,%5,%6,%7}, {%8,%9}, {%0,%1,%2,%3};"
                    : "+f"(c0[0]), "+f"(c0[1]), "+f"(c0[2]), "+f"(c0[3])
                    : "r"(a0), "r"(a1), "r"(a2), "r"(a3),
                      "r"(b0), "r"(b1));
            }
        }
    }

    // ---- epilogue: O / l
    const float inv0 = 1.f / l0;
    const float inv1 = 1.f / l1;
    float* o0 = O + (((size_t)(b*S_ + row0)*NH + h) << 6) + tig*2;
    float* o1 = O + (((size_t)(b*S_ + row1)*NH + h) << 6) + tig*2;
#pragma unroll
    for (int nf = 0; nf < 8; nf++) {
        *(float2*)(o0 + nf*8) = make_float2(oacc[nf][0]*inv0, oacc[nf][1]*inv0);
        *(float2*)(o1 + nf*8) = make_float2(oacc[nf][2]*inv1, oacc[nf][3]*inv1);
    }
}

// ---------------------------------------------------------------------------
extern "C" void kernel_launch(void* const* d_in, const int* in_sizes, int n_in,
                              void* d_out, int out_size)
{
    const float* x    = (const float*)d_in[0];
    const float* cosT = (const float*)d_in[1];
    const float* sinT = (const float*)d_in[2];
    const float* wq   = (const float*)d_in[3];
    const float* wk   = (const float*)d_in[4];
    const float* wv   = (const float*)d_in[5];
    const float* wo   = (const float*)d_in[6];
    float* out = (float*)d_out;

    float *Q, *K, *V, *Aat;
    cudaGetSymbolAddress((void**)&Q,   g_Q);
    cudaGetSymbolAddress((void**)&K,   g_K);
    cudaGetSymbolAddress((void**)&V,   g_V);
    cudaGetSymbolAddress((void**)&Aat, g_A);

    // Projections (tf32 tensor cores)
    sgemm_tf32<<<dim3(HID/128,       MROWS/128), 256>>>(x, wq, Q, MROWS, HID,     HID);
    sgemm_tf32<<<dim3((NKV*HD)/128,  MROWS/128), 256>>>(x, wk, K, MROWS, NKV*HD,  HID);
    sgemm_tf32<<<dim3((NKV*HD)/128,  MROWS/128), 256>>>(x, wv, V, MROWS, NKV*HD,  HID);

    // RoPE on Q and K
    int totq = MROWS * NH  * 32;
    int totk = MROWS * NKV * 32;
    rope_kernel<<<(totq+255)/256, 256>>>(Q, cosT, sinT, NH,  totq);
    rope_kernel<<<(totk+255)/256, 256>>>(K, cosT, sinT, NKV, totk);

    // Tensor-core causal GQA flash attention
    cudaFuncSetAttribute(flash_attn_mma, cudaFuncAttributeMaxDynamicSharedMemorySize, FA_SMEM);
    flash_attn_mma<<<dim3(NH, S_/128, B_), 256, FA_SMEM>>>(Q, K, V, Aat);

    // Output projection (tf32 tensor cores)
    sgemm_tf32<<<dim3(HID/128, MROWS/128), 256>>>(Aat, wo, out, MROWS, HID, HID);
}

// round 5
// speedup vs baseline: 12.1280x; 1.3100x over previous
#include <cuda_runtime.h>
#include <math.h>

#define B_  2
#define S_  2048
#define HID 1024
#define NH  16
#define NKV 4
#define HD  64
#define MROWS (B_*S_)   // 4096

// Scratch (no cudaMalloc allowed)
__device__ float g_Q[MROWS * HID];        // [B,S,NH,HD]
__device__ float g_K[MROWS * NKV * HD];   // [B,S,NKV,HD]
__device__ float g_V[MROWS * NKV * HD];
__device__ float g_A[MROWS * HID];        // attention output [B,S,NH,HD]

__device__ __forceinline__ unsigned f2tf32(float x) {
    unsigned r;
    asm("cvt.rna.tf32.f32 %0, %1;" : "=r"(r) : "f"(x));
    return r;
}

// ---------------------------------------------------------------------------
// tf32 tensor-core GEMM:  C[M,N] = A[M,K] @ W[N,K]^T  (row-major A and W)
// 128x128 block, BK=32, 256 threads (8 warps), warp tile 32x64 (mf2 x nf8).
// Optional fused RoPE on the output (rope != 0): pairs (i, i+32) of each
// 64-wide head live in (nf, nf+4) of the same thread.
// ---------------------------------------------------------------------------
#define TST 36

__global__ __launch_bounds__(256) void sgemm_tf32(
    const float* __restrict__ A, const float* __restrict__ W,
    float* __restrict__ C, int M, int N, int K,
    const float* __restrict__ cosT, const float* __restrict__ sinT, int rope)
{
    __shared__ unsigned As[128*TST];
    __shared__ unsigned Bs[128*TST];

    const int t    = threadIdx.x;
    const int wid  = t >> 5;
    const int lane = t & 31;
    const int grp  = lane >> 2;
    const int tig  = lane & 3;
    const int wm   = (wid >> 1) * 32;   // 4 row-warps
    const int wn   = (wid & 1) * 64;    // 2 col-warps

    const float* Ab = A + (size_t)(blockIdx.y * 128) * K;
    const float* Wb = W + (size_t)(blockIdx.x * 128) * K;

    float acc[2][8][4];
#pragma unroll
    for (int mf = 0; mf < 2; mf++)
#pragma unroll
        for (int nf = 0; nf < 8; nf++) {
            acc[mf][nf][0]=0.f; acc[mf][nf][1]=0.f;
            acc[mf][nf][2]=0.f; acc[mf][nf][3]=0.f;
        }

    for (int k0 = 0; k0 < K; k0 += 32) {
#pragma unroll
        for (int i = 0; i < 4; i++) {
            int idx = t + i * 256;
            int r   = idx >> 3;
            int c4  = (idx & 7) * 4;
            float4 av = *(const float4*)(Ab + (size_t)r * K + k0 + c4);
            float4 bv = *(const float4*)(Wb + (size_t)r * K + k0 + c4);
            unsigned* ad = &As[r*TST + c4];
            ad[0]=f2tf32(av.x); ad[1]=f2tf32(av.y); ad[2]=f2tf32(av.z); ad[3]=f2tf32(av.w);
            unsigned* bd = &Bs[r*TST + c4];
            bd[0]=f2tf32(bv.x); bd[1]=f2tf32(bv.y); bd[2]=f2tf32(bv.z); bd[3]=f2tf32(bv.w);
        }
        __syncthreads();

#pragma unroll
        for (int k8 = 0; k8 < 4; k8++) {
            const int kb = k8 * 8;
            unsigned af[2][4];
#pragma unroll
            for (int mf = 0; mf < 2; mf++) {
                int m = wm + mf*16 + grp;
                af[mf][0] = As[(m  )*TST + kb + tig];
                af[mf][1] = As[(m+8)*TST + kb + tig];
                af[mf][2] = As[(m  )*TST + kb + tig + 4];
                af[mf][3] = As[(m+8)*TST + kb + tig + 4];
            }
#pragma unroll
            for (int nf = 0; nf < 8; nf++) {
                int n = wn + nf*8 + grp;
                unsigned b0 = Bs[n*TST + kb + tig];
                unsigned b1 = Bs[n*TST + kb + tig + 4];
#pragma unroll
                for (int mf = 0; mf < 2; mf++) {
                    float* c0 = &acc[mf][nf][0];
                    asm volatile(
                        "mma.sync.aligned.m16n8k8.row.col.f32.tf32.tf32.f32 "
                        "{%0,%1,%2,%3}, {%4,%5,%6,%7}, {%8,%9}, {%0,%1,%2,%3};"
                        : "+f"(c0[0]), "+f"(c0[1]), "+f"(c0[2]), "+f"(c0[3])
                        : "r"(af[mf][0]), "r"(af[mf][1]), "r"(af[mf][2]), "r"(af[mf][3]),
                          "r"(b0), "r"(b1));
                }
            }
        }
        __syncthreads();
    }

    // Optional fused RoPE: lo cols are nf<4 (i = nf*8+tig*2 < 32), hi = nf+4.
    if (rope) {
#pragma unroll
        for (int mf = 0; mf < 2; mf++) {
#pragma unroll
            for (int nf = 0; nf < 4; nf++) {
                const int i0 = nf*8 + tig*2;   // col % 64, < 32
#pragma unroll
                for (int hh = 0; hh < 2; hh++) {      // rows grp, grp+8
                    int row = blockIdx.y*128 + wm + mf*16 + grp + hh*8;
                    int s   = row & (S_ - 1);
#pragma unroll
                    for (int j = 0; j < 2; j++) {
                        float c  = cosT[s*HD + i0 + j];
                        float sn = sinT[s*HD + i0 + j];
                        float L = acc[mf][nf  ][hh*2 + j];
                        float H = acc[mf][nf+4][hh*2 + j];
                        acc[mf][nf  ][hh*2 + j] = L*c - H*sn;
                        acc[mf][nf+4][hh*2 + j] = H*c + L*sn;
                    }
                }
            }
        }
    }

#pragma unroll
    for (int mf = 0; mf < 2; mf++) {
#pragma unroll
        for (int nf = 0; nf < 8; nf++) {
            float* c0 = &acc[mf][nf][0];
            int row = blockIdx.y*128 + wm + mf*16 + grp;
            int col = blockIdx.x*128 + wn + nf*8 + tig*2;
            *(float2*)(C + (size_t)row*N + col)     = make_float2(c0[0], c0[1]);
            *(float2*)(C + (size_t)(row+8)*N + col) = make_float2(c0[2], c0[3]);
        }
    }
}

// ---------------------------------------------------------------------------
// Tensor-core causal flash attention v3 (tf32 mma.sync.m16n8k8).
// grid (NH, S/128, B), 128 threads (4 warps). BM=128 -> 32 q-rows per warp
// (mf=2 m16 fragments). BN=64. Each K/V B-fragment feeds 2 MMAs, and only
// 4 warps load B -> smem crossbar traffic halved vs R4.
// ---------------------------------------------------------------------------
#define FST 68
#define FA_SMEM ((64*FST*2 + 128*FST) * 4)   // Ks + Vs + Ps = 69632 B

__global__ __launch_bounds__(128) void flash_attn_mma3(
    const float* __restrict__ Q, const float* __restrict__ K,
    const float* __restrict__ V, float* __restrict__ O)
{
    extern __shared__ unsigned fsm[];
    unsigned* Ks = fsm;              // [64][FST]
    unsigned* Vs = Ks + 64*FST;      // [64][FST]
    unsigned* Ps = Vs + 64*FST;      // [128][FST]

    const int h  = blockIdx.x;
    const int bm = (gridDim.y - 1) - blockIdx.y;   // heaviest blocks first
    const int b  = blockIdx.z;
    const int hk = h >> 2;                          // GQA
    const int t    = threadIdx.x;
    const int w    = t >> 5;
    const int lane = t & 31;
    const int grp  = lane >> 2;
    const int tig  = lane & 3;
    const int rb   = bm*128 + w*32;   // warp's first q row (global)

    // ---- Q fragments: 2 mf x 8 kb x 4 regs, scaled by 1/8, tf32
    unsigned qf[2][8][4];
#pragma unroll
    for (int mf = 0; mf < 2; mf++) {
        const float* q0 = Q + (((size_t)(b*S_ + rb + mf*16 + grp    )*NH + h) << 6);
        const float* q1 = Q + (((size_t)(b*S_ + rb + mf*16 + grp + 8)*NH + h) << 6);
#pragma unroll
        for (int kb = 0; kb < 8; kb++) {
            qf[mf][kb][0] = f2tf32(0.125f * q0[kb*8 + tig]);
            qf[mf][kb][1] = f2tf32(0.125f * q1[kb*8 + tig]);
            qf[mf][kb][2] = f2tf32(0.125f * q0[kb*8 + tig + 4]);
            qf[mf][kb][3] = f2tf32(0.125f * q1[kb*8 + tig + 4]);
        }
    }

    float oacc[2][8][4];
#pragma unroll
    for (int mf = 0; mf < 2; mf++)
#pragma unroll
        for (int nf = 0; nf < 8; nf++) {
            oacc[mf][nf][0]=0.f; oacc[mf][nf][1]=0.f;
            oacc[mf][nf][2]=0.f; oacc[mf][nf][3]=0.f;
        }
    float m[4]  = {-1e30f, -1e30f, -1e30f, -1e30f};
    float l[4]  = {0.f, 0.f, 0.f, 0.f};

    const int ntiles = 2*(bm + 1);
    for (int tile = 0; tile < ntiles; tile++) {
        __syncthreads();
        // ---- load K,V tile (64 keys x 64 dims), convert to tf32
#pragma unroll
        for (int i = 0; i < 8; i++) {
            int idx = t + i*128;
            int r   = idx >> 4;
            int c4  = (idx & 15) * 4;
            size_t gb = (((size_t)(b*S_ + tile*64 + r)*NKV + hk) << 6) + c4;
            float4 kv = *(const float4*)(K + gb);
            float4 vv = *(const float4*)(V + gb);
            unsigned* kd = &Ks[r*FST + c4];
            kd[0]=f2tf32(kv.x); kd[1]=f2tf32(kv.y); kd[2]=f2tf32(kv.z); kd[3]=f2tf32(kv.w);
            unsigned* vd = &Vs[r*FST + c4];
            vd[0]=f2tf32(vv.x); vd[1]=f2tf32(vv.y); vd[2]=f2tf32(vv.z); vd[3]=f2tf32(vv.w);
        }
        __syncthreads();

        // ---- S = (Q/8) K^T : per warp 32x64
        float sacc[2][8][4];
#pragma unroll
        for (int mf = 0; mf < 2; mf++)
#pragma unroll
            for (int nf = 0; nf < 8; nf++) {
                sacc[mf][nf][0]=0.f; sacc[mf][nf][1]=0.f;
                sacc[mf][nf][2]=0.f; sacc[mf][nf][3]=0.f;
            }
#pragma unroll
        for (int kb = 0; kb < 8; kb++) {
#pragma unroll
            for (int nf = 0; nf < 8; nf++) {
                unsigned b0 = Ks[(nf*8+grp)*FST + kb*8 + tig];
                unsigned b1 = Ks[(nf*8+grp)*FST + kb*8 + tig + 4];
#pragma unroll
                for (int mf = 0; mf < 2; mf++) {
                    float* c0 = &sacc[mf][nf][0];
                    asm volatile(
                        "mma.sync.aligned.m16n8k8.row.col.f32.tf32.tf32.f32 "
                        "{%0,%1,%2,%3}, {%4,%5,%6,%7}, {%8,%9}, {%0,%1,%2,%3};"
                        : "+f"(c0[0]), "+f"(c0[1]), "+f"(c0[2]), "+f"(c0[3])
                        : "r"(qf[mf][kb][0]), "r"(qf[mf][kb][1]),
                          "r"(qf[mf][kb][2]), "r"(qf[mf][kb][3]),
                          "r"(b0), "r"(b1));
                }
            }
        }

        // ---- online softmax on fragment layout
        const bool diag = (tile >= 2*bm);
        const int colb = tile*64;
#pragma unroll
        for (int mf = 0; mf < 2; mf++) {
            const int r0 = rb + mf*16 + grp;
            const int r1 = r0 + 8;
            float mt0 = -1e30f, mt1 = -1e30f;
#pragma unroll
            for (int nf = 0; nf < 8; nf++) {
                const int c0i = colb + nf*8 + tig*2;
                if (diag) {
                    if (c0i     > r0) sacc[mf][nf][0] = -1e30f;
                    if (c0i + 1 > r0) sacc[mf][nf][1] = -1e30f;
                    if (c0i     > r1) sacc[mf][nf][2] = -1e30f;
                    if (c0i + 1 > r1) sacc[mf][nf][3] = -1e30f;
                }
                mt0 = fmaxf(mt0, fmaxf(sacc[mf][nf][0], sacc[mf][nf][1]));
                mt1 = fmaxf(mt1, fmaxf(sacc[mf][nf][2], sacc[mf][nf][3]));
            }
            mt0 = fmaxf(mt0, __shfl_xor_sync(0xffffffffu, mt0, 1));
            mt0 = fmaxf(mt0, __shfl_xor_sync(0xffffffffu, mt0, 2));
            mt1 = fmaxf(mt1, __shfl_xor_sync(0xffffffffu, mt1, 1));
            mt1 = fmaxf(mt1, __shfl_xor_sync(0xffffffffu, mt1, 2));

            const float mn0 = fmaxf(m[mf*2  ], mt0);
            const float mn1 = fmaxf(m[mf*2+1], mt1);
            const float cr0 = __expf(m[mf*2  ] - mn0);
            const float cr1 = __expf(m[mf*2+1] - mn1);
            float ps0 = 0.f, ps1 = 0.f;

            unsigned* P0 = &Ps[(w*32 + mf*16 + grp)*FST + tig*2];
            unsigned* P1 = P0 + 8*FST;
#pragma unroll
            for (int nf = 0; nf < 8; nf++) {
                float p00 = __expf(sacc[mf][nf][0] - mn0);
                float p01 = __expf(sacc[mf][nf][1] - mn0);
                float p10 = __expf(sacc[mf][nf][2] - mn1);
                float p11 = __expf(sacc[mf][nf][3] - mn1);
                ps0 += p00 + p01;
                ps1 += p10 + p11;
                *(uint2*)(P0 + nf*8) = make_uint2(f2tf32(p00), f2tf32(p01));
                *(uint2*)(P1 + nf*8) = make_uint2(f2tf32(p10), f2tf32(p11));
            }
            ps0 += __shfl_xor_sync(0xffffffffu, ps0, 1);
            ps0 += __shfl_xor_sync(0xffffffffu, ps0, 2);
            ps1 += __shfl_xor_sync(0xffffffffu, ps1, 1);
            ps1 += __shfl_xor_sync(0xffffffffu, ps1, 2);
            l[mf*2  ] = l[mf*2  ]*cr0 + ps0;  m[mf*2  ] = mn0;
            l[mf*2+1] = l[mf*2+1]*cr1 + ps1;  m[mf*2+1] = mn1;
#pragma unroll
            for (int nf = 0; nf < 8; nf++) {
                oacc[mf][nf][0] *= cr0; oacc[mf][nf][1] *= cr0;
                oacc[mf][nf][2] *= cr1; oacc[mf][nf][3] *= cr1;
            }
        }
        __syncwarp();   // Ps region is warp-private

        // ---- O += P V
#pragma unroll
        for (int kb = 0; kb < 8; kb++) {
            unsigned a[2][4];
#pragma unroll
            for (int mf = 0; mf < 2; mf++) {
                const int pr = w*32 + mf*16 + grp;
                a[mf][0] = Ps[(pr    )*FST + kb*8 + tig];
                a[mf][1] = Ps[(pr + 8)*FST + kb*8 + tig];
                a[mf][2] = Ps[(pr    )*FST + kb*8 + tig + 4];
                a[mf][3] = Ps[(pr + 8)*FST + kb*8 + tig + 4];
            }
#pragma unroll
            for (int nf = 0; nf < 8; nf++) {
                unsigned b0 = Vs[(kb*8 + tig    )*FST + nf*8 + grp];
                unsigned b1 = Vs[(kb*8 + tig + 4)*FST + nf*8 + grp];
#pragma unroll
                for (int mf = 0; mf < 2; mf++) {
                    float* c0 = &oacc[mf][nf][0];
                    asm volatile(
                        "mma.sync.aligned.m16n8k8.row.col.f32.tf32.tf32.f32 "
                        "{%0,%1,%2,%3}, {%4,%5,%6,%7}, {%8,%9}, {%0,%1,%2,%3};"
                        : "+f"(c0[0]), "+f"(c0[1]), "+f"(c0[2]), "+f"(c0[3])
                        : "r"(a[mf][0]), "r"(a[mf][1]), "r"(a[mf][2]), "r"(a[mf][3]),
                          "r"(b0), "r"(b1));
                }
            }
        }
    }

    // ---- epilogue: O / l
#pragma unroll
    for (int mf = 0; mf < 2; mf++) {
        const float inv0 = 1.f / l[mf*2];
        const float inv1 = 1.f / l[mf*2+1];
        float* o0 = O + (((size_t)(b*S_ + rb + mf*16 + grp    )*NH + h) << 6) + tig*2;
        float* o1 = O + (((size_t)(b*S_ + rb + mf*16 + grp + 8)*NH + h) << 6) + tig*2;
#pragma unroll
        for (int nf = 0; nf < 8; nf++) {
            *(float2*)(o0 + nf*8) = make_float2(oacc[mf][nf][0]*inv0, oacc[mf][nf][1]*inv0);
            *(float2*)(o1 + nf*8) = make_float2(oacc[mf][nf][2]*inv1, oacc[mf][nf][3]*inv1);
        }
    }
}

// ---------------------------------------------------------------------------
extern "C" void kernel_launch(void* const* d_in, const int* in_sizes, int n_in,
                              void* d_out, int out_size)
{
    const float* x    = (const float*)d_in[0];
    const float* cosT = (const float*)d_in[1];
    const float* sinT = (const float*)d_in[2];
    const float* wq   = (const float*)d_in[3];
    const float* wk   = (const float*)d_in[4];
    const float* wv   = (const float*)d_in[5];
    const float* wo   = (const float*)d_in[6];
    float* out = (float*)d_out;

    float *Q, *K, *V, *Aat;
    cudaGetSymbolAddress((void**)&Q,   g_Q);
    cudaGetSymbolAddress((void**)&K,   g_K);
    cudaGetSymbolAddress((void**)&V,   g_V);
    cudaGetSymbolAddress((void**)&Aat, g_A);

    // Projections (tf32 tensor cores); RoPE fused into Q/K epilogues
    sgemm_tf32<<<dim3(HID/128,       MROWS/128), 256>>>(x, wq, Q, MROWS, HID,    HID, cosT, sinT, 1);
    sgemm_tf32<<<dim3((NKV*HD)/128,  MROWS/128), 256>>>(x, wk, K, MROWS, NKV*HD, HID, cosT, sinT, 1);
    sgemm_tf32<<<dim3((NKV*HD)/128,  MROWS/128), 256>>>(x, wv, V, MROWS, NKV*HD, HID, cosT, sinT, 0);

    // Tensor-core causal GQA flash attention
    cudaFuncSetAttribute(flash_attn_mma3, cudaFuncAttributeMaxDynamicSharedMemorySize, FA_SMEM);
    flash_attn_mma3<<<dim3(NH, S_/128, B_), 128, FA_SMEM>>>(Q, K, V, Aat);

    // Output projection (tf32 tensor cores)
    sgemm_tf32<<<dim3(HID/128, MROWS/128), 256>>>(Aat, wo, out, MROWS, HID, HID, cosT, sinT, 0);
}